// round 7
// baseline (speedup 1.0000x reference)
#include <cuda_runtime.h>
#include <cuda_bf16.h>
#include <cstdint>
#include <math.h>

#define S_LEN   4096
#define E_DIM   2048
#define H_NUM   16
#define D_HEAD  128
#define HD      2048
#define NQKV    6144
#define T_TILES 32
#define K_ANCH  8
#define TILE    128

// ---------------------------------------------------------------------------
// Device-global scratch
// ---------------------------------------------------------------------------
__device__ __nv_bfloat16 g_qkvh[S_LEN * NQKV];   // post-RoPE bf16 hi
__device__ __nv_bfloat16 g_qkvl[S_LEN * NQKV];   // post-RoPE bf16 lo

__device__ __nv_bfloat16 g_xhi[S_LEN * E_DIM];
__device__ __nv_bfloat16 g_xlo[S_LEN * E_DIM];
__device__ __nv_bfloat16 g_ahi[S_LEN * HD];
__device__ __nv_bfloat16 g_alo[S_LEN * HD];

__device__ __nv_bfloat16 g_wt_hi[NQKV * E_DIM];   // [wq|wk|wv]^T, K-major
__device__ __nv_bfloat16 g_wt_lo[NQKV * E_DIM];
__device__ __nv_bfloat16 g_wot_hi[E_DIM * HD];
__device__ __nv_bfloat16 g_wot_lo[E_DIM * HD];

// ---------------------------------------------------------------------------
// PTX helpers (family-agnostic)
// ---------------------------------------------------------------------------
__device__ __forceinline__ uint32_t smem_u32(const void* p) {
    uint32_t a;
    asm("{ .reg .u64 t; cvta.to.shared.u64 t, %1; cvt.u32.u64 %0, t; }" : "=r"(a) : "l"(p));
    return a;
}
__device__ __forceinline__ void cp16(uint32_t dst, const void* src) {
    asm volatile("cp.async.cg.shared.global [%0], [%1], 16;" :: "r"(dst), "l"(src));
}
__device__ __forceinline__ void cp_commit() {
    asm volatile("cp.async.commit_group;" ::: "memory");
}
template<int N>
__device__ __forceinline__ void cp_wait() {
    asm volatile("cp.async.wait_group %0;" :: "n"(N) : "memory");
}
__device__ __forceinline__ void ldm_x4(uint32_t* r, uint32_t addr) {
    asm volatile("ldmatrix.sync.aligned.m8n8.x4.shared.b16 {%0,%1,%2,%3}, [%4];"
        : "=r"(r[0]), "=r"(r[1]), "=r"(r[2]), "=r"(r[3]) : "r"(addr));
}
__device__ __forceinline__ void ldm_x4_t(uint32_t* r, uint32_t addr) {
    asm volatile("ldmatrix.sync.aligned.m8n8.x4.trans.shared.b16 {%0,%1,%2,%3}, [%4];"
        : "=r"(r[0]), "=r"(r[1]), "=r"(r[2]), "=r"(r[3]) : "r"(addr));
}
__device__ __forceinline__ void mma_bf16(float* d, const uint32_t* a, const uint32_t* b) {
    asm volatile(
        "mma.sync.aligned.m16n8k16.row.col.f32.bf16.bf16.f32 "
        "{%0,%1,%2,%3}, {%4,%5,%6,%7}, {%8,%9}, {%0,%1,%2,%3};"
        : "+f"(d[0]), "+f"(d[1]), "+f"(d[2]), "+f"(d[3])
        : "r"(a[0]), "r"(a[1]), "r"(a[2]), "r"(a[3]), "r"(b[0]), "r"(b[1]));
}
__device__ __forceinline__ uint32_t pack_bf16(float lo, float hi) {
    uint32_t d;
    asm("cvt.rn.bf16x2.f32 %0, %1, %2;" : "=r"(d) : "f"(hi), "f"(lo));
    return d;
}
__device__ __forceinline__ void split8(const float* v, uint4& H, uint4& L) {
    uint32_t hw[4], lw[4];
#pragma unroll
    for (int j = 0; j < 4; j++) {
        float a = v[2 * j], b = v[2 * j + 1];
        hw[j] = pack_bf16(a, b);
        lw[j] = pack_bf16(a - __uint_as_float(hw[j] << 16),
                          b - __uint_as_float(hw[j] & 0xffff0000u));
    }
    H = make_uint4(hw[0], hw[1], hw[2], hw[3]);
    L = make_uint4(lw[0], lw[1], lw[2], lw[3]);
}

// ---------------------------------------------------------------------------
// Split-bf16 tensor-core GEMM: C = A * Bt^T.
// mode 0: fp32 C. mode 1 (QKV): RoPE (blockIdx.x<32) + hi/lo split epilogue.
// Inner loop: B fragments double-buffered per 16-row panel so ldmatrix
// issues overlap the 24 mmas of the previous panel.
// ---------------------------------------------------------------------------
#define GSEC   10240
#define GSTAGE (4 * GSEC)
#define GSMEM  (2 * GSTAGE)

__device__ __forceinline__ void g_load_stage(
    uint32_t sb, const __nv_bfloat16* pAh, const __nv_bfloat16* pAl,
    const __nv_bfloat16* pBh, const __nv_bfloat16* pBl, int K, int tid)
{
    const __nv_bfloat16* secp[4] = {pAh, pAl, pBh, pBl};
#pragma unroll
    for (int idx = tid; idx < 2048; idx += 128) {
        int row = idx >> 2, ch = idx & 3;
        int sec = row >> 7, r = row & 127;
        cp16(sb + sec * GSEC + r * 80 + ch * 16, secp[sec] + (size_t)r * K + ch * 8);
    }
}

__global__ __launch_bounds__(128, 2) void gemm_tc(
    const __nv_bfloat16* __restrict__ Ahi, const __nv_bfloat16* __restrict__ Alo,
    const __nv_bfloat16* __restrict__ Bhi, const __nv_bfloat16* __restrict__ Blo,
    float* __restrict__ C,
    __nv_bfloat16* __restrict__ qh, __nv_bfloat16* __restrict__ ql,
    const float* __restrict__ ang,
    int M, int N, int K, int mode)
{
    extern __shared__ char sm[];
    const uint32_t sb = smem_u32(sm);
    const int tid = threadIdx.x;
    const int wid = tid >> 5, lane = tid & 31;
    const int wm = wid >> 1, wn = wid & 1;
    const int g = lane >> 2, t = lane & 3;
    const int lrow = lane & 15, lk2 = (lane >> 4) * 16;
    const int brow = (lane & 7) + ((lane >> 4) & 1) * 8;
    const int bk2 = ((lane >> 3) & 1) * 16;
    const int mBase = blockIdx.y * 128;
    const int nBase = blockIdx.x * 128;
    const int nch = K / 32;

    float acc[4][8][4];
#pragma unroll
    for (int i = 0; i < 4; i++)
#pragma unroll
        for (int j = 0; j < 8; j++)
#pragma unroll
            for (int r = 0; r < 4; r++) acc[i][j][r] = 0.f;

    const __nv_bfloat16* pAh = Ahi + (size_t)mBase * K;
    const __nv_bfloat16* pAl = Alo + (size_t)mBase * K;
    const __nv_bfloat16* pBh = Bhi + (size_t)nBase * K;
    const __nv_bfloat16* pBl = Blo + (size_t)nBase * K;

    g_load_stage(sb, pAh, pAl, pBh, pBl, K, tid);
    cp_commit();

    for (int c = 0; c < nch; c++) {
        if (c + 1 < nch) {
            g_load_stage(sb + ((c + 1) & 1) * GSTAGE,
                         pAh + (c + 1) * 32, pAl + (c + 1) * 32,
                         pBh + (c + 1) * 32, pBl + (c + 1) * 32, K, tid);
            cp_commit();
            cp_wait<1>();
        } else {
            cp_wait<0>();
        }
        __syncthreads();

        const uint32_t st = sb + (c & 1) * GSTAGE;

#pragma unroll
        for (int ks = 0; ks < 2; ks++) {
            uint32_t ah[4][4], al[4][4], bh[2][4], bl[2][4];
#pragma unroll
            for (int mb = 0; mb < 4; mb++) {
                uint32_t ao = (uint32_t)(wm * 64 + mb * 16 + lrow) * 80 + ks * 32 + lk2;
                ldm_x4(ah[mb], st + ao);
                ldm_x4(al[mb], st + GSEC + ao);
            }
            // prefetch B panel 0 (hi+lo)
            {
                uint32_t bo = (uint32_t)(wn * 64 + brow) * 80 + ks * 32 + bk2;
                ldm_x4(bh[0], st + 2 * GSEC + bo);
                ldm_x4(bl[0], st + 3 * GSEC + bo);
            }
#pragma unroll
            for (int p = 0; p < 4; p++) {
                const int cur = p & 1, nxt = cur ^ 1;
                if (p < 3) {
                    uint32_t bo = (uint32_t)(wn * 64 + (p + 1) * 16 + brow) * 80 + ks * 32 + bk2;
                    ldm_x4(bh[nxt], st + 2 * GSEC + bo);
                    ldm_x4(bl[nxt], st + 3 * GSEC + bo);
                }
#pragma unroll
                for (int mb = 0; mb < 4; mb++) {
                    mma_bf16(acc[mb][2 * p],     ah[mb], bh[cur]);
                    mma_bf16(acc[mb][2 * p + 1], ah[mb], bh[cur] + 2);
                }
#pragma unroll
                for (int mb = 0; mb < 4; mb++) {
                    mma_bf16(acc[mb][2 * p],     al[mb], bh[cur]);
                    mma_bf16(acc[mb][2 * p + 1], al[mb], bh[cur] + 2);
                }
#pragma unroll
                for (int mb = 0; mb < 4; mb++) {
                    mma_bf16(acc[mb][2 * p],     ah[mb], bl[cur]);
                    mma_bf16(acc[mb][2 * p + 1], ah[mb], bl[cur] + 2);
                }
            }
        }
        __syncthreads();
    }

    if (mode == 0) {
#pragma unroll
        for (int mb = 0; mb < 4; mb++) {
#pragma unroll
            for (int nb = 0; nb < 8; nb++) {
                int row = mBase + wm * 64 + mb * 16 + g;
                int col = nBase + wn * 64 + nb * 8 + t * 2;
                *(float2*)(C + (size_t)row * N + col) = make_float2(acc[mb][nb][0], acc[mb][nb][1]);
                *(float2*)(C + (size_t)(row + 8) * N + col) = make_float2(acc[mb][nb][2], acc[mb][nb][3]);
            }
        }
        return;
    }

    // ---- mode 1: RoPE (Q|K tiles) + hi/lo bf16 split epilogue ----
    float* cs = (float*)sm;
#pragma unroll
    for (int mb = 0; mb < 4; mb++) {
#pragma unroll
        for (int nb = 0; nb < 8; nb++) {
            int r0 = wm * 64 + mb * 16 + g;
            int cl = wn * 64 + nb * 8 + t * 2;
            *(float2*)(cs + r0 * 132 + cl) = make_float2(acc[mb][nb][0], acc[mb][nb][1]);
            *(float2*)(cs + (r0 + 8) * 132 + cl) = make_float2(acc[mb][nb][2], acc[mb][nb][3]);
        }
    }
    __syncthreads();

    const bool doRope = (blockIdx.x < 32);
    const int cch = tid & 7;
    const int rg  = tid >> 3;
#pragma unroll 1
    for (int itr = 0; itr < 8; itr++) {
        int r = rg + itr * 16;
        int srow = mBase + r;
        float f0[8], f1[8], o0[8], o1[8];
        *(float4*)(f0)     = *(float4*)(cs + r * 132 + cch * 8);
        *(float4*)(f0 + 4) = *(float4*)(cs + r * 132 + cch * 8 + 4);
        *(float4*)(f1)     = *(float4*)(cs + r * 132 + cch * 8 + 64);
        *(float4*)(f1 + 4) = *(float4*)(cs + r * 132 + cch * 8 + 68);
        if (doRope) {
            float av[8];
            *(float4*)(av)     = *(const float4*)(ang + (size_t)srow * 64 + cch * 8);
            *(float4*)(av + 4) = *(const float4*)(ang + (size_t)srow * 64 + cch * 8 + 4);
#pragma unroll
            for (int j = 0; j < 8; j++) {
                float cc = __cosf(av[j]), ss = __sinf(av[j]);
                o0[j] = f0[j] * cc - f1[j] * ss;
                o1[j] = f1[j] * cc + f0[j] * ss;
            }
        } else {
#pragma unroll
            for (int j = 0; j < 8; j++) { o0[j] = f0[j]; o1[j] = f1[j]; }
        }
        uint4 H, L;
        size_t base = (size_t)srow * NQKV + nBase + cch * 8;
        split8(o0, H, L);
        *(uint4*)(qh + base) = H;
        *(uint4*)(ql + base) = L;
        split8(o1, H, L);
        *(uint4*)(qh + base + 64) = H;
        *(uint4*)(ql + base + 64) = L;
    }
}

// ---------------------------------------------------------------------------
// fp32 -> bf16 hi/lo split (elementwise, for x)
// ---------------------------------------------------------------------------
__global__ __launch_bounds__(256) void conv_hilo(
    const float* __restrict__ A, __nv_bfloat16* __restrict__ hi,
    __nv_bfloat16* __restrict__ lo, int n4)
{
    int i = blockIdx.x * blockDim.x + threadIdx.x;
    if (i >= n4) return;
    float4 v = ((const float4*)A)[i];
    float f[4] = {v.x, v.y, v.z, v.w};
    uint32_t hw[2] = {0, 0}, lw[2] = {0, 0};
#pragma unroll
    for (int j = 0; j < 4; j++) {
        __nv_bfloat16 h = __float2bfloat16(f[j]);
        float rem = f[j] - __bfloat162float(h);
        __nv_bfloat16 l = __float2bfloat16(rem);
        hw[j >> 1] |= (uint32_t)__bfloat16_as_ushort(h) << ((j & 1) * 16);
        lw[j >> 1] |= (uint32_t)__bfloat16_as_ushort(l) << ((j & 1) * 16);
    }
    ((uint2*)hi)[i] = make_uint2(hw[0], hw[1]);
    ((uint2*)lo)[i] = make_uint2(lw[0], lw[1]);
}

// ---------------------------------------------------------------------------
// Weight transpose + split
// ---------------------------------------------------------------------------
__device__ __forceinline__ void wt_body(
    const float* W, __nv_bfloat16* hi, __nv_bfloat16* lo, int K, int N, int outOff)
{
    __shared__ float tb[32][33];
    const int n0 = blockIdx.x * 32, k0 = blockIdx.y * 32;
    const int tx = threadIdx.x, ty = threadIdx.y;
#pragma unroll
    for (int i = 0; i < 4; i++)
        tb[ty + i * 8][tx] = W[(size_t)(k0 + ty + i * 8) * N + n0 + tx];
    __syncthreads();
#pragma unroll
    for (int i = 0; i < 4; i++) {
        int n = outOff + n0 + ty + i * 8;
        float v = tb[tx][ty + i * 8];
        __nv_bfloat16 h = __float2bfloat16(v);
        float rem = v - __bfloat162float(h);
        hi[(size_t)n * K + k0 + tx] = h;
        lo[(size_t)n * K + k0 + tx] = __float2bfloat16(rem);
    }
}

__global__ __launch_bounds__(256) void convWT3(
    const float* __restrict__ W0, const float* __restrict__ W1,
    const float* __restrict__ W2, __nv_bfloat16* __restrict__ hi,
    __nv_bfloat16* __restrict__ lo)
{
    const float* W = (blockIdx.z == 0) ? W0 : (blockIdx.z == 1) ? W1 : W2;
    wt_body(W, hi, lo, E_DIM, HD, blockIdx.z * HD);
}

__global__ __launch_bounds__(256) void convWT(
    const float* __restrict__ W, __nv_bfloat16* __restrict__ hi,
    __nv_bfloat16* __restrict__ lo, int K, int N)
{
    wt_body(W, hi, lo, K, N, 0);
}

// ---------------------------------------------------------------------------
// Tensor-core block-sparse flash attention (split-bf16, 3-term), pipelined
// smem loads + double-buffered fragment loads.
// ---------------------------------------------------------------------------
#define APITCH 136
#define ASEC   (128 * APITCH)
#define AQH 0
#define AQL (1 * ASEC)
#define AKH (2 * ASEC)
#define AKL (3 * ASEC)
#define AVH (4 * ASEC)
#define AVL (5 * ASEC)
#define ATT_SMEM (6 * ASEC * 2)

__global__ __launch_bounds__(256, 1) void attn_tc(
    const __nv_bfloat16* __restrict__ qkvh, const __nv_bfloat16* __restrict__ qkvl,
    const int* __restrict__ anchors,
    __nv_bfloat16* __restrict__ oh, __nv_bfloat16* __restrict__ ol)
{
    extern __shared__ __nv_bfloat16 asmem[];
    const uint32_t sb = smem_u32(asmem);
    const int t = blockIdx.x, h = blockIdx.y;
    const int tid = threadIdx.x, wid = tid >> 5, lane = tid & 31;
    const int g = lane >> 2, tq = lane & 3;
    const int lrow = lane & 15, lk2 = (lane >> 4) * 16;
    const int brow = (lane & 7) + ((lane >> 4) & 1) * 8;
    const int bk2 = ((lane >> 3) & 1) * 16;
    const int vm = lane >> 3, vr = lane & 7;
    const float sm_scale = 0.08838834764831845f;

    int sels[K_ANCH + 1], nt = 0;
#pragma unroll
    for (int it = 0; it < K_ANCH; it++) {
        int s = anchors[(h * T_TILES + t) * K_ANCH + it];
        if (s <= t) sels[nt++] = s;
    }
    sels[nt++] = t;

    auto loadsec = [&](uint32_t sec, const __nv_bfloat16* src) {
#pragma unroll
        for (int i = tid; i < 2048; i += 256) {
            int row = i >> 4, ch = i & 15;
            cp16(sb + (sec + row * APITCH) * 2 + ch * 16, src + (size_t)row * NQKV + ch * 8);
        }
    };
    const size_t hoff = (size_t)h * D_HEAD;

    loadsec(AQH, qkvh + (size_t)(t * TILE) * NQKV + hoff);
    loadsec(AQL, qkvl + (size_t)(t * TILE) * NQKV + hoff);
    loadsec(AKH, qkvh + (size_t)(sels[0] * TILE) * NQKV + HD + hoff);
    loadsec(AKL, qkvl + (size_t)(sels[0] * TILE) * NQKV + HD + hoff);
    cp_commit();
    loadsec(AVH, qkvh + (size_t)(sels[0] * TILE) * NQKV + 2 * HD + hoff);
    loadsec(AVL, qkvl + (size_t)(sels[0] * TILE) * NQKV + 2 * HD + hoff);
    cp_commit();

    float o[16][4];
#pragma unroll
    for (int i = 0; i < 16; i++)
#pragma unroll
        for (int j = 0; j < 4; j++) o[i][j] = 0.f;
    float m0 = -INFINITY, m1 = -INFINITY, l0 = 0.f, l1 = 0.f;

    for (int jt = 0; jt < nt; jt++) {
        const int sel = sels[jt];

        cp_wait<1>();
        __syncthreads();

        // ---- S = Q K^T (3-term, double-buffered K panels) ----
        float S[16][4];
#pragma unroll
        for (int i = 0; i < 16; i++)
#pragma unroll
            for (int j = 0; j < 4; j++) S[i][j] = 0.f;

#pragma unroll
        for (int ks = 0; ks < 8; ks++) {
            uint32_t ah[4], al[4], kh[2][4], kl[2][4];
            uint32_t ao = (uint32_t)((wid * 16 + lrow) * APITCH) * 2 + ks * 32 + lk2;
            ldm_x4(ah, sb + AQH * 2 + ao);
            ldm_x4(al, sb + AQL * 2 + ao);
            {
                uint32_t bo = (uint32_t)(brow * APITCH) * 2 + ks * 32 + bk2;
                ldm_x4(kh[0], sb + AKH * 2 + bo);
                ldm_x4(kl[0], sb + AKL * 2 + bo);
            }
#pragma unroll
            for (int p = 0; p < 8; p++) {
                const int cur = p & 1, nxt = cur ^ 1;
                if (p < 7) {
                    uint32_t bo = (uint32_t)(((p + 1) * 16 + brow) * APITCH) * 2 + ks * 32 + bk2;
                    ldm_x4(kh[nxt], sb + AKH * 2 + bo);
                    ldm_x4(kl[nxt], sb + AKL * 2 + bo);
                }
                mma_bf16(S[2 * p],     ah, kh[cur]);
                mma_bf16(S[2 * p + 1], ah, kh[cur] + 2);
                mma_bf16(S[2 * p],     al, kh[cur]);
                mma_bf16(S[2 * p + 1], al, kh[cur] + 2);
                mma_bf16(S[2 * p],     ah, kl[cur]);
                mma_bf16(S[2 * p + 1], ah, kl[cur] + 2);
            }
        }
        __syncthreads();

        if (jt + 1 < nt) {
            loadsec(AKH, qkvh + (size_t)(sels[jt + 1] * TILE) * NQKV + HD + hoff);
            loadsec(AKL, qkvl + (size_t)(sels[jt + 1] * TILE) * NQKV + HD + hoff);
        }
        cp_commit();

        // ---- online softmax ----
        const bool diag = (sel == t);
        const int qr0 = wid * 16 + g;
        float mx0 = -INFINITY, mx1 = -INFINITY;
#pragma unroll
        for (int nb = 0; nb < 16; nb++) {
            int c0 = nb * 8 + tq * 2, c1 = c0 + 1;
            float v0 = S[nb][0] * sm_scale, v1 = S[nb][1] * sm_scale;
            float v2 = S[nb][2] * sm_scale, v3 = S[nb][3] * sm_scale;
            if (diag) {
                if (c0 > qr0) v0 = -INFINITY;
                if (c1 > qr0) v1 = -INFINITY;
                if (c0 > qr0 + 8) v2 = -INFINITY;
                if (c1 > qr0 + 8) v3 = -INFINITY;
            }
            S[nb][0] = v0; S[nb][1] = v1; S[nb][2] = v2; S[nb][3] = v3;
            mx0 = fmaxf(mx0, fmaxf(v0, v1));
            mx1 = fmaxf(mx1, fmaxf(v2, v3));
        }
        mx0 = fmaxf(mx0, __shfl_xor_sync(0xffffffffu, mx0, 1));
        mx0 = fmaxf(mx0, __shfl_xor_sync(0xffffffffu, mx0, 2));
        mx1 = fmaxf(mx1, __shfl_xor_sync(0xffffffffu, mx1, 1));
        mx1 = fmaxf(mx1, __shfl_xor_sync(0xffffffffu, mx1, 2));

        float mn0 = fmaxf(m0, mx0), mn1 = fmaxf(m1, mx1);
        float fs0 = __expf(m0 - mn0), fs1 = __expf(m1 - mn1);
        m0 = mn0; m1 = mn1;

        float rs0 = 0.f, rs1 = 0.f;
#pragma unroll
        for (int nb = 0; nb < 16; nb++) {
            float p0 = __expf(S[nb][0] - mn0);
            float p1 = __expf(S[nb][1] - mn0);
            float p2 = __expf(S[nb][2] - mn1);
            float p3 = __expf(S[nb][3] - mn1);
            S[nb][0] = p0; S[nb][1] = p1; S[nb][2] = p2; S[nb][3] = p3;
            rs0 += p0 + p1; rs1 += p2 + p3;
        }
        rs0 += __shfl_xor_sync(0xffffffffu, rs0, 1);
        rs0 += __shfl_xor_sync(0xffffffffu, rs0, 2);
        rs1 += __shfl_xor_sync(0xffffffffu, rs1, 1);
        rs1 += __shfl_xor_sync(0xffffffffu, rs1, 2);
        l0 = l0 * fs0 + rs0;
        l1 = l1 * fs1 + rs1;
#pragma unroll
        for (int nb = 0; nb < 16; nb++) {
            o[nb][0] *= fs0; o[nb][1] *= fs0;
            o[nb][2] *= fs1; o[nb][3] *= fs1;
        }

        cp_wait<1>();
        __syncthreads();

        // ---- O += P V (3-term, double-buffered V panels) ----
#pragma unroll
        for (int j = 0; j < 8; j++) {
            uint32_t ph[4], pl[4];
            float p00 = S[2 * j][0],     p01 = S[2 * j][1];
            float p10 = S[2 * j][2],     p11 = S[2 * j][3];
            float q00 = S[2 * j + 1][0], q01 = S[2 * j + 1][1];
            float q10 = S[2 * j + 1][2], q11 = S[2 * j + 1][3];
            ph[0] = pack_bf16(p00, p01);
            ph[1] = pack_bf16(p10, p11);
            ph[2] = pack_bf16(q00, q01);
            ph[3] = pack_bf16(q10, q11);
            pl[0] = pack_bf16(p00 - __uint_as_float(ph[0] << 16),
                              p01 - __uint_as_float(ph[0] & 0xffff0000u));
            pl[1] = pack_bf16(p10 - __uint_as_float(ph[1] << 16),
                              p11 - __uint_as_float(ph[1] & 0xffff0000u));
            pl[2] = pack_bf16(q00 - __uint_as_float(ph[2] << 16),
                              q01 - __uint_as_float(ph[2] & 0xffff0000u));
            pl[3] = pack_bf16(q10 - __uint_as_float(ph[3] << 16),
                              q11 - __uint_as_float(ph[3] & 0xffff0000u));

            uint32_t vrow = (uint32_t)(j * 16 + (vm & 1) * 8 + vr) * APITCH * 2;
            uint32_t vh[2][4], vl[2][4];
            {
                uint32_t vo = vrow + (uint32_t)((vm >> 1) * 16);
                ldm_x4_t(vh[0], sb + AVH * 2 + vo);
                ldm_x4_t(vl[0], sb + AVL * 2 + vo);
            }
#pragma unroll
            for (int p = 0; p < 8; p++) {
                const int cur = p & 1, nxt = cur ^ 1;
                if (p < 7) {
                    uint32_t vo = vrow + (uint32_t)((p + 1) * 32 + (vm >> 1) * 16);
                    ldm_x4_t(vh[nxt], sb + AVH * 2 + vo);
                    ldm_x4_t(vl[nxt], sb + AVL * 2 + vo);
                }
                mma_bf16(o[2 * p],     ph, vh[cur]);
                mma_bf16(o[2 * p + 1], ph, vh[cur] + 2);
                mma_bf16(o[2 * p],     pl, vh[cur]);
                mma_bf16(o[2 * p + 1], pl, vh[cur] + 2);
                mma_bf16(o[2 * p],     ph, vl[cur]);
                mma_bf16(o[2 * p + 1], ph, vl[cur] + 2);
            }
        }
        __syncthreads();

        if (jt + 1 < nt) {
            loadsec(AVH, qkvh + (size_t)(sels[jt + 1] * TILE) * NQKV + 2 * HD + hoff);
            loadsec(AVL, qkvl + (size_t)(sels[jt + 1] * TILE) * NQKV + 2 * HD + hoff);
        }
        cp_commit();
    }

    // ---- epilogue: bf16 hi/lo out ----
    float inv0 = 1.0f / l0, inv1 = 1.0f / l1;
    int row0 = t * TILE + wid * 16 + g;
#pragma unroll
    for (int nb = 0; nb < 16; nb++) {
        size_t i0 = (size_t)row0 * HD + h * D_HEAD + nb * 8 + tq * 2;
        size_t i1 = i0 + (size_t)8 * HD;
        float a0 = o[nb][0] * inv0, a1 = o[nb][1] * inv0;
        float b0 = o[nb][2] * inv1, b1 = o[nb][3] * inv1;
        uint32_t hw = pack_bf16(a0, a1);
        *(uint32_t*)(oh + i0) = hw;
        *(uint32_t*)(ol + i0) = pack_bf16(a0 - __uint_as_float(hw << 16),
                                          a1 - __uint_as_float(hw & 0xffff0000u));
        hw = pack_bf16(b0, b1);
        *(uint32_t*)(oh + i1) = hw;
        *(uint32_t*)(ol + i1) = pack_bf16(b0 - __uint_as_float(hw << 16),
                                          b1 - __uint_as_float(hw & 0xffff0000u));
    }
}

// ---------------------------------------------------------------------------
// Launch
// ---------------------------------------------------------------------------
extern "C" void kernel_launch(void* const* d_in, const int* in_sizes, int n_in,
                              void* d_out, int out_size)
{
    (void)in_sizes; (void)n_in; (void)out_size;
    const float* x   = (const float*)d_in[0];
    const float* wq  = (const float*)d_in[1];
    const float* wk  = (const float*)d_in[2];
    const float* wv  = (const float*)d_in[3];
    const float* wo  = (const float*)d_in[4];
    const float* ang = (const float*)d_in[5];
    const int* anchors = (const int*)d_in[6];
    float* out = (float*)d_out;

    __nv_bfloat16 *qkvh, *qkvl, *xhi, *xlo, *ahi, *alo, *wth, *wtl, *woh, *wol;
    cudaGetSymbolAddress((void**)&qkvh, g_qkvh);
    cudaGetSymbolAddress((void**)&qkvl, g_qkvl);
    cudaGetSymbolAddress((void**)&xhi, g_xhi);
    cudaGetSymbolAddress((void**)&xlo, g_xlo);
    cudaGetSymbolAddress((void**)&ahi, g_ahi);
    cudaGetSymbolAddress((void**)&alo, g_alo);
    cudaGetSymbolAddress((void**)&wth, g_wt_hi);
    cudaGetSymbolAddress((void**)&wtl, g_wt_lo);
    cudaGetSymbolAddress((void**)&woh, g_wot_hi);
    cudaGetSymbolAddress((void**)&wol, g_wot_lo);

    cudaFuncSetAttribute(gemm_tc, cudaFuncAttributeMaxDynamicSharedMemorySize, GSMEM);
    cudaFuncSetAttribute(attn_tc, cudaFuncAttributeMaxDynamicSharedMemorySize, ATT_SMEM);

    const int n4x = S_LEN * E_DIM / 4;
    conv_hilo<<<(n4x + 255) / 256, 256>>>(x, xhi, xlo, n4x);
    convWT3<<<dim3(HD / 32, E_DIM / 32, 3), dim3(32, 8)>>>(wq, wk, wv, wth, wtl);
    convWT<<<dim3(E_DIM / 32, HD / 32), dim3(32, 8)>>>(wo, woh, wol, HD, E_DIM);

    gemm_tc<<<dim3(NQKV / 128, S_LEN / 128), 128, GSMEM>>>(
        xhi, xlo, wth, wtl, nullptr, qkvh, qkvl, ang, S_LEN, NQKV, E_DIM, 1);

    attn_tc<<<dim3(T_TILES, H_NUM), 256, ATT_SMEM>>>(qkvh, qkvl, anchors, ahi, alo);

    gemm_tc<<<dim3(E_DIM / 128, S_LEN / 128), 128, GSMEM>>>(
        ahi, alo, woh, wol, out, nullptr, nullptr, nullptr, S_LEN, E_DIM, HD, 0);
}